// round 12
// baseline (speedup 1.0000x reference)
#include <cuda_runtime.h>
#include <math.h>

#define NN 4096
#define FF 256
#define EE 65536
#define MAXD 96      // max 1-hop degree incl diag (Poisson(16); huge margin)
#define MAXR 2048    // max 2-hop neighborhood size (observed ~300-700)

// ---------------- device scratch (allocation-free rule: __device__ globals) ----
// g_A: transient scatter buffer. Zero-initialized at module load; every launch
//      returns it to all-zeros via the atomicExch dedup pass (self-cleaning).
__device__ float g_A [(size_t)NN * NN];
// g_A2: sparse adj_k store. Written only at A2-nonzero off-diag positions;
//      untouched cells stay 0 from static init.
__device__ float g_A2[(size_t)NN * NN];
__device__ int   g_nbrCnt[NN];
__device__ int   g_nbrCol[NN * MAXD];
__device__ float g_nbrVal[NN * MAXD];
__device__ int   g_D[NN];
__device__ float g_sq[NN];
__device__ unsigned long long g_S1;   // sum D   (integer -> exact, order-free)
__device__ unsigned long long g_S2;   // sum D^2

// ---------------- kernels -----------------------------------------------------

// Fused: edge scatter + squared norms + per-launch counter reset.
// grid = 256 blocks x 256 threads = 2048 warps; each warp does 2 nodes' norms.
__global__ void k_scatter(const int* __restrict__ ei, const float* __restrict__ w,
                          const float* __restrict__ X)
{
    int i = blockIdx.x * blockDim.x + threadIdx.x;
    int warp = i >> 5, lane = i & 31;

    // squared norms (fixed reduction order; warp-uniform loops)
#pragma unroll
    for (int r = 0; r < 2; r++) {
        int u = warp + r * 2048;
        const float* x = X + (size_t)u * FF;
        float s = 0.f;
#pragma unroll
        for (int k = 0; k < FF / 32; k++) { float a = x[lane + 32 * k]; s += a * a; }
#pragma unroll
        for (int o = 16; o; o >>= 1) s += __shfl_xor_sync(0xffffffffu, s, o);
        if (lane == 0) g_sq[u] = s;
    }

    if (i < NN) g_nbrCnt[i] = 0;
    if (i == 0) { g_S1 = 0ull; g_S2 = 0ull; }
    if (i < EE) {
        int u = ei[i];
        int v = ei[EE + i];
        atomicAdd(&g_A[(size_t)u * NN + v], w[i]);
    }
}

// dedup via atomicExch: winner gets the summed weight, cell is restored to 0.
// Builds compact per-row neighbor lists (clamped values). Self-loops are
// claimed+cleaned but not appended (diag handled separately, value == 1).
__global__ void k_build(const int* __restrict__ ei)
{
    int i = blockIdx.x * blockDim.x + threadIdx.x;
    if (i >= EE) return;
    int u = ei[i];
    int v = ei[EE + i];
    float val = atomicExch(&g_A[(size_t)u * NN + v], 0.f);
    if (val != 0.f && u != v) {
        int p = atomicAdd(&g_nbrCnt[u], 1);
        if (p < MAXD - 1) {
            g_nbrCol[u * MAXD + p] = v;
            g_nbrVal[u * MAXD + p] = fminf(val, 1.f);   // clamp A>1 -> 1
        }
    }
}

// append diag (==1 exactly), finalize D, accumulate integer degree stats.
__global__ void k_diag()
{
    int u = blockIdx.x * blockDim.x + threadIdx.x;
    if (u >= NN) return;
    int c = g_nbrCnt[u]; if (c > MAXD - 1) c = MAXD - 1;
    g_nbrCol[u * MAXD + c] = u;
    g_nbrVal[u * MAXD + c] = 1.f;
    g_nbrCnt[u] = c + 1;
    g_D[u] = c;                                  // off-diag nonzero count
    atomicAdd(&g_S1, (unsigned long long)c);
    atomicAdd(&g_S2, (unsigned long long)((long long)c * c));
}

// Fused per-row kernel: SpGEMM row in smem -> compact -> branch -> sparse write.
__global__ void __launch_bounds__(256) k_main(const float* __restrict__ X)
{
    __shared__ float  acc  [NN];     // 16 KB  A2 row accumulator
    __shared__ int    scol [MAXR];   //  8 KB
    __shared__ float  sdist[MAXR];   //  8 KB
    __shared__ float  xu   [FF];     //  1 KB
    __shared__ int    ucol [MAXD];
    __shared__ float  uval [MAXD];
    __shared__ int    cntS;
    __shared__ double s_dth;

    int u      = blockIdx.x;
    int tid    = threadIdx.x;
    int warpid = tid >> 5, lane = tid & 31;

    for (int i = tid; i < NN; i += 256) acc[i] = 0.f;
    int cnt = g_nbrCnt[u];
    if (tid < cnt) { ucol[tid] = g_nbrCol[u * MAXD + tid];
                     uval[tid] = g_nbrVal[u * MAXD + tid]; }
    for (int f = tid; f < FF; f += 256) xu[f] = X[(size_t)u * FF + f];
    if (tid == 0) {
        cntS = 0;
        // d_thres = mean(D) + 2*std(D) from exact integer sums
        double S1 = (double)g_S1, S2 = (double)g_S2;
        double mean = S1 / (double)NN;
        double var  = S2 / (double)NN - mean * mean;
        if (var < 0.0) var = 0.0;
        s_dth = mean + 2.0 * sqrt(var);
    }
    __syncthreads();

    // SpGEMM: warps take k-entries in parallel; smem atomicAdd accumulation.
    // All products are positive -> nonzero pattern is order-independent; the
    // summed values enter the output linearly (ulp-order noise only).
    for (int t = warpid; t < cnt; t += 8) {
        int   k = ucol[t];
        float a = uval[t];
        int  ck = g_nbrCnt[k];
        const int*   kc = g_nbrCol + k * MAXD;
        const float* kv = g_nbrVal + k * MAXD;
        for (int e = lane; e < ck; e += 32)
            atomicAdd(&acc[kc[e]], a * kv[e]);
    }
    __syncthreads();

    // compact off-diag nonzeros (order irrelevant: all downstream is set-based)
    for (int c = tid; c < NN; c += 256) {
        if (acc[c] != 0.f && c != u) {
            int p = atomicAdd(&cntS, 1);
            if (p < MAXR) scol[p] = c;
        }
    }
    __syncthreads();

    int Dr = cntS; if (Dr > MAXR) Dr = MAXR;
    int D  = g_D[u];
    bool highD = ((double)D > s_dth);
    int  nz    = Dr - 2 * D;

    float* outrow = g_A2 + (size_t)u * NN;

    if (highD) {
        // Z = (A == 0): keep A2-A only at 1-hop edges
        for (int i = tid; i < Dr; i += 256) {
            int c = scol[i];
            float a = 0.f;
            for (int j = 0; j < cnt; j++) if (ucol[j] == c) { a = uval[j]; break; }
            outrow[c] = (a != 0.f) ? (acc[c] - a) : 0.f;
        }
    } else if (nz < 0) {
        // no-sparse branch: adj_k = A2 - A everywhere
        for (int i = tid; i < Dr; i += 256) {
            int c = scol[i];
            float a = 0.f;
            for (int j = 0; j < cnt; j++) if (ucol[j] == c) { a = uval[j]; break; }
            outrow[c] = acc[c] - a;
        }
    } else if (nz == 0) {
        // nz_eff = n -> all neighbors selected -> entire row zero
        for (int i = tid; i < Dr; i += 256) outrow[scol[i]] = 0.f;
    } else {
        // sparse branch: zero the nz farthest (stable-tie) neighbors.
        float squ = g_sq[u];

        // Warp-uniform neighbor batches: each warp owns 4 consecutive
        // neighbors per iteration (one per 8-lane group). ALL lanes execute
        // every iteration -> full-mask shuffles are legal; inactive groups
        // are predicated only on loads/stores. 8 LDG.128/lane in flight.
        int grp4 = lane >> 3;                 // group within warp, 0..3
        int gl   = lane & 7;
        const float4* xu4 = reinterpret_cast<const float4*>(xu);
        for (int i0 = warpid * 4; i0 < Dr; i0 += 32) {
            int  i   = i0 + grp4;
            bool act = (i < Dr);
            int  v   = scol[act ? i : 0];     // Dr >= 1 in this branch
            const float4* xv4 = reinterpret_cast<const float4*>(X + (size_t)v * FF);
            float s = 0.f;
#pragma unroll
            for (int m = 0; m < 8; m++) {
                float4 a = xv4[gl + 8 * m];
                float4 b = xu4[gl + 8 * m];
                s += a.x * b.x;  s += a.y * b.y;
                s += a.z * b.z;  s += a.w * b.w;
            }
            s += __shfl_xor_sync(0xffffffffu, s, 4);
            s += __shfl_xor_sync(0xffffffffu, s, 2);
            s += __shfl_xor_sync(0xffffffffu, s, 1);
            if (gl == 0 && act) sdist[i] = squ + g_sq[v] - 2.f * s;
        }
        __syncthreads();

        // rank(v) = #{d_j > d_v} + #{d_j == d_v, col_j < col_v} (stable argsort)
        for (int i = tid; i < Dr; i += 256) {
            float di = sdist[i];
            int   ci = scol[i];
            int r = 0;
            int j = 0;
#pragma unroll 4
            for (; j + 4 <= Dr; j += 4) {
#pragma unroll
                for (int q = 0; q < 4; q++) {
                    float dj = sdist[j + q];
                    r += (dj > di) || (dj == di && scol[j + q] < ci);
                }
            }
            for (; j < Dr; j++) {
                float dj = sdist[j];
                r += (dj > di) || (dj == di && scol[j] < ci);
            }
            float out;
            if (r < nz) out = 0.f;
            else {
                float a = 0.f;
                for (int t = 0; t < cnt; t++) if (ucol[t] == ci) { a = uval[t]; break; }
                out = acc[ci] - a;
            }
            outrow[ci] = out;
        }
    }
    // diag of adj_k is 0: never written -> stays 0 from static init
}

__global__ void k_edge(const int* __restrict__ ei, const float* __restrict__ w,
                       const float* __restrict__ t1, const float* __restrict__ t2,
                       float* __restrict__ out)
{
    int i = blockIdx.x * blockDim.x + threadIdx.x;
    if (i < EE) {
        int u = ei[i];
        int v = ei[EE + i];
        float val = t1[0] * w[i] + t2[0] * g_A2[(size_t)u * NN + v];
        out[i] = fmaxf(val, 0.f);
    }
}

// ---------------- launch ------------------------------------------------------

extern "C" void kernel_launch(void* const* d_in, const int* in_sizes, int n_in,
                              void* d_out, int out_size)
{
    (void)in_sizes; (void)n_in; (void)out_size;
    const int*   edge_index = (const int*)  d_in[0];   // (2, E) int32
    const float* edge_w     = (const float*)d_in[1];   // (E,)
    const float* features   = (const float*)d_in[2];   // (N, F)
    const float* theta_1    = (const float*)d_in[3];   // (1,)
    const float* theta_2    = (const float*)d_in[4];   // (1,)
    float*       out        = (float*)      d_out;     // (E,)

    k_scatter<<<EE / 256, 256>>>(edge_index, edge_w, features);
    k_build  <<<EE / 256, 256>>>(edge_index);
    k_diag   <<<NN / 256, 256>>>();
    k_main   <<<NN,       256>>>(features);
    k_edge   <<<EE / 256, 256>>>(edge_index, edge_w, theta_1, theta_2, out);
}

// round 15
// speedup vs baseline: 1.4972x; 1.4972x over previous
#include <cuda_runtime.h>
#include <math.h>

#define NN 4096
#define FF 256
#define EE 65536
#define MAXD 96      // max 1-hop degree incl diag (Poisson(16); huge margin)
#define MAXR 2048    // max 2-hop neighborhood size (observed ~300-700)

// ---------------- device scratch (allocation-free rule: __device__ globals) ----
// g_A: transient scatter buffer. Zero-initialized at module load; every launch
//      returns it to all-zeros via the atomicExch dedup pass (self-cleaning).
__device__ float g_A [(size_t)NN * NN];
// g_A2: sparse adj_k store. Written only at A2-nonzero off-diag positions;
//      untouched cells stay 0 from static init.
__device__ float g_A2[(size_t)NN * NN];
__device__ int   g_nbrCnt[NN];
__device__ int   g_nbrCol[NN * MAXD];
__device__ float g_nbrVal[NN * MAXD];
__device__ int   g_D[NN];
__device__ float g_sq[NN];
__device__ unsigned long long g_S1;   // sum D   (integer -> exact, order-free)
__device__ unsigned long long g_S2;   // sum D^2

// ---------------- kernels -----------------------------------------------------

// Fused: edge scatter + squared norms + per-launch counter reset.
__global__ void k_scatter(const int* __restrict__ ei, const float* __restrict__ w,
                          const float* __restrict__ X)
{
    int i = blockIdx.x * blockDim.x + threadIdx.x;
    int warp = i >> 5, lane = i & 31;

    // squared norms (fixed reduction order; warp-uniform loops)
#pragma unroll
    for (int r = 0; r < 2; r++) {
        int u = warp + r * 2048;
        const float* x = X + (size_t)u * FF;
        float s = 0.f;
#pragma unroll
        for (int k = 0; k < FF / 32; k++) { float a = x[lane + 32 * k]; s += a * a; }
#pragma unroll
        for (int o = 16; o; o >>= 1) s += __shfl_xor_sync(0xffffffffu, s, o);
        if (lane == 0) g_sq[u] = s;
    }

    if (i < NN) g_nbrCnt[i] = 0;
    if (i == 0) { g_S1 = 0ull; g_S2 = 0ull; }
    if (i < EE) {
        int u = ei[i];
        int v = ei[EE + i];
        atomicAdd(&g_A[(size_t)u * NN + v], w[i]);
    }
}

// dedup via atomicExch: winner gets the summed weight, cell is restored to 0.
__global__ void k_build(const int* __restrict__ ei)
{
    int i = blockIdx.x * blockDim.x + threadIdx.x;
    if (i >= EE) return;
    int u = ei[i];
    int v = ei[EE + i];
    float val = atomicExch(&g_A[(size_t)u * NN + v], 0.f);
    if (val != 0.f && u != v) {
        int p = atomicAdd(&g_nbrCnt[u], 1);
        if (p < MAXD - 1) {
            g_nbrCol[u * MAXD + p] = v;
            g_nbrVal[u * MAXD + p] = fminf(val, 1.f);   // clamp A>1 -> 1
        }
    }
}

// append diag (==1 exactly), finalize D, accumulate integer degree stats.
__global__ void k_diag()
{
    int u = blockIdx.x * blockDim.x + threadIdx.x;
    if (u >= NN) return;
    int c = g_nbrCnt[u]; if (c > MAXD - 1) c = MAXD - 1;
    g_nbrCol[u * MAXD + c] = u;
    g_nbrVal[u * MAXD + c] = 1.f;
    g_nbrCnt[u] = c + 1;
    g_D[u] = c;                                  // off-diag nonzero count
    atomicAdd(&g_S1, (unsigned long long)c);
    atomicAdd(&g_S2, (unsigned long long)((long long)c * c));
}

// Fused per-row kernel: SpGEMM row in smem -> compact -> branch -> sparse write.
// Top-nz selection done with an O(Dr) radix select instead of O(Dr^2) ranking.
__global__ void __launch_bounds__(256, 5) k_main(const float* __restrict__ X)
{
    __shared__ float    acc  [NN];     // 16 KB  A2 row accumulator
    __shared__ int      scol [MAXR];   //  8 KB
    __shared__ unsigned skey [MAXR];   //  8 KB  order-preserving distance keys
    __shared__ float    xu   [FF];     //  1 KB
    __shared__ int      ucol [MAXD];
    __shared__ float    uval [MAXD];
    __shared__ int      hist [256];    //  1 KB
    __shared__ int      cntS, s_need, s_cGT;
    __shared__ unsigned s_prefix;
    __shared__ double   s_dth;

    int u      = blockIdx.x;
    int tid    = threadIdx.x;
    int warpid = tid >> 5, lane = tid & 31;

    for (int i = tid; i < NN; i += 256) acc[i] = 0.f;
    int cnt = g_nbrCnt[u];
    if (tid < cnt) { ucol[tid] = g_nbrCol[u * MAXD + tid];
                     uval[tid] = g_nbrVal[u * MAXD + tid]; }
    for (int f = tid; f < FF; f += 256) xu[f] = X[(size_t)u * FF + f];
    if (tid == 0) {
        cntS = 0;
        // d_thres = mean(D) + 2*std(D) from exact integer sums
        double S1 = (double)g_S1, S2 = (double)g_S2;
        double mean = S1 / (double)NN;
        double var  = S2 / (double)NN - mean * mean;
        if (var < 0.0) var = 0.0;
        s_dth = mean + 2.0 * sqrt(var);
    }
    __syncthreads();

    // SpGEMM: warps take k-entries in parallel; smem atomicAdd accumulation.
    // Products all positive -> nonzero pattern exact regardless of order.
    for (int t = warpid; t < cnt; t += 8) {
        int   k = ucol[t];
        float a = uval[t];
        int  ck = g_nbrCnt[k];
        const int*   kc = g_nbrCol + k * MAXD;
        const float* kv = g_nbrVal + k * MAXD;
        for (int e = lane; e < ck; e += 32)
            atomicAdd(&acc[kc[e]], a * kv[e]);
    }
    __syncthreads();

    // compact off-diag nonzeros (order irrelevant: all downstream is set-based)
    for (int c = tid; c < NN; c += 256) {
        if (acc[c] != 0.f && c != u) {
            int p = atomicAdd(&cntS, 1);
            if (p < MAXR) scol[p] = c;
        }
    }
    __syncthreads();

    int Dr = cntS; if (Dr > MAXR) Dr = MAXR;
    int D  = g_D[u];
    bool highD = ((double)D > s_dth);
    int  nz    = Dr - 2 * D;

    float* outrow = g_A2 + (size_t)u * NN;

    if (highD) {
        // Z = (A == 0): keep A2-A only at 1-hop edges
        for (int i = tid; i < Dr; i += 256) {
            int c = scol[i];
            float a = 0.f;
            for (int j = 0; j < cnt; j++) if (ucol[j] == c) { a = uval[j]; break; }
            outrow[c] = (a != 0.f) ? (acc[c] - a) : 0.f;
        }
    } else if (nz < 0) {
        // no-sparse branch: adj_k = A2 - A everywhere
        for (int i = tid; i < Dr; i += 256) {
            int c = scol[i];
            float a = 0.f;
            for (int j = 0; j < cnt; j++) if (ucol[j] == c) { a = uval[j]; break; }
            outrow[c] = acc[c] - a;
        }
    } else if (nz == 0) {
        // nz_eff = n -> all neighbors selected -> entire row zero
        for (int i = tid; i < Dr; i += 256) outrow[scol[i]] = 0.f;
    } else {
        // sparse branch: zero the nz farthest (stable-tie) neighbors.
        float squ = g_sq[u];

        // Distances -> order-preserving uint keys.
        // Warp-uniform batches: 4 neighbors per warp-iteration (8-lane groups),
        // full-mask shuffles legal; 8 LDG.128/lane in flight.
        int grp4 = lane >> 3, gl = lane & 7;
        const float4* xu4 = reinterpret_cast<const float4*>(xu);
        for (int i0 = warpid * 4; i0 < Dr; i0 += 32) {
            int  i   = i0 + grp4;
            bool act = (i < Dr);
            int  v   = scol[act ? i : 0];     // Dr >= 1 in this branch
            const float4* xv4 = reinterpret_cast<const float4*>(X + (size_t)v * FF);
            float s = 0.f;
#pragma unroll
            for (int m = 0; m < 8; m++) {
                float4 a = xv4[gl + 8 * m];
                float4 b = xu4[gl + 8 * m];
                s += a.x * b.x;  s += a.y * b.y;
                s += a.z * b.z;  s += a.w * b.w;
            }
            s += __shfl_xor_sync(0xffffffffu, s, 4);
            s += __shfl_xor_sync(0xffffffffu, s, 2);
            s += __shfl_xor_sync(0xffffffffu, s, 1);
            if (gl == 0 && act) {
                float d = squ + g_sq[v] - 2.f * s;
                unsigned bits = __float_as_uint(d);
                unsigned key  = (bits & 0x80000000u) ? ~bits : (bits | 0x80000000u);
                if (key == 0x7FFFFFFFu) key = 0x80000000u;   // -0.0 == +0.0
                skey[i] = key;
            }
        }
        if (tid == 0) { s_prefix = 0u; s_need = nz; }
        __syncthreads();

        // Radix select: T = key of the nz-th largest element (1-indexed).
        // 4 byte-passes, high to low.
#pragma unroll
        for (int pass = 0; pass < 4; pass++) {
            int shift = 24 - 8 * pass;
            hist[tid] = 0;                 // blockDim == 256 == #bins
            __syncthreads();
            unsigned pref = s_prefix;
            for (int i = tid; i < Dr; i += 256) {
                unsigned k = skey[i];
                bool in = (pass == 0) || ((k >> (shift + 8)) == pref);
                if (in) atomicAdd(&hist[(k >> shift) & 0xffu], 1);
            }
            __syncthreads();
            if (tid == 0) {
                int need = s_need;
                int b = 255;
                for (;; b--) { int h = hist[b]; if (need - h <= 0) break; need -= h; }
                s_need   = need;
                s_prefix = (s_prefix << 8) | (unsigned)b;
            }
            __syncthreads();
        }
        unsigned T = s_prefix;

        // cGT = #{key > T} (exact integer count, order-free)
        if (tid == 0) s_cGT = 0;
        __syncthreads();
        {
            int local = 0;
            for (int i = tid; i < Dr; i += 256) local += (skey[i] > T);
#pragma unroll
            for (int o = 16; o; o >>= 1) local += __shfl_xor_sync(0xffffffffu, local, o);
            if (lane == 0 && local) atomicAdd(&s_cGT, local);
        }
        __syncthreads();
        int tieSel = nz - s_cGT;    // slots left for ties, filled by ascending col

        for (int i = tid; i < Dr; i += 256) {
            unsigned k  = skey[i];
            int      ci = scol[i];
            bool zero;
            if (k > T) zero = true;
            else if (k == T) {
                int tr = 0;
                for (int j = 0; j < Dr; j++)
                    tr += (skey[j] == T && scol[j] < ci);
                zero = (tr < tieSel);
            } else zero = false;

            float out;
            if (zero) out = 0.f;
            else {
                float a = 0.f;
                for (int t = 0; t < cnt; t++) if (ucol[t] == ci) { a = uval[t]; break; }
                out = acc[ci] - a;
            }
            outrow[ci] = out;
        }
    }
    // diag of adj_k is 0: never written -> stays 0 from static init
}

__global__ void k_edge(const int* __restrict__ ei, const float* __restrict__ w,
                       const float* __restrict__ t1, const float* __restrict__ t2,
                       float* __restrict__ out)
{
    int i = blockIdx.x * blockDim.x + threadIdx.x;
    if (i < EE) {
        int u = ei[i];
        int v = ei[EE + i];
        float val = t1[0] * w[i] + t2[0] * g_A2[(size_t)u * NN + v];
        out[i] = fmaxf(val, 0.f);
    }
}

// ---------------- launch ------------------------------------------------------

extern "C" void kernel_launch(void* const* d_in, const int* in_sizes, int n_in,
                              void* d_out, int out_size)
{
    (void)in_sizes; (void)n_in; (void)out_size;
    const int*   edge_index = (const int*)  d_in[0];   // (2, E) int32
    const float* edge_w     = (const float*)d_in[1];   // (E,)
    const float* features   = (const float*)d_in[2];   // (N, F)
    const float* theta_1    = (const float*)d_in[3];   // (1,)
    const float* theta_2    = (const float*)d_in[4];   // (1,)
    float*       out        = (float*)      d_out;     // (E,)

    k_scatter<<<EE / 256, 256>>>(edge_index, edge_w, features);
    k_build  <<<EE / 256, 256>>>(edge_index);
    k_diag   <<<NN / 256, 256>>>();
    k_main   <<<NN,       256>>>(features);
    k_edge   <<<EE / 256, 256>>>(edge_index, edge_w, theta_1, theta_2, out);
}

// round 16
// speedup vs baseline: 1.9027x; 1.2708x over previous
#include <cuda_runtime.h>
#include <math.h>

#define NN 4096
#define FF 256
#define EE 65536
#define MAXD 96      // max 1-hop degree incl diag (Poisson(16); huge margin)
#define MAXR 2048    // max 2-hop neighborhood size (observed ~300-700)

// ---------------- device scratch (allocation-free rule: __device__ globals) ----
// g_A: transient scatter buffer. Zero-initialized at module load; every launch
//      returns it to all-zeros via the atomicExch dedup pass (self-cleaning).
__device__ float g_A [(size_t)NN * NN];
// g_A2: sparse adj_k store. Written only at A2-nonzero off-diag positions;
//      untouched cells stay 0 from static init.
__device__ float g_A2[(size_t)NN * NN];
__device__ int   g_nbrCnt[NN];
__device__ int   g_nbrCol[NN * MAXD];
__device__ float g_nbrVal[NN * MAXD];
__device__ int   g_D[NN];
__device__ float g_sq[NN];
__device__ unsigned long long g_S1;   // sum D   (integer -> exact, order-free)
__device__ unsigned long long g_S2;   // sum D^2

// ---------------- kernels -----------------------------------------------------

// Fused: edge scatter + squared norms + per-launch counter reset.
__global__ void k_scatter(const int* __restrict__ ei, const float* __restrict__ w,
                          const float* __restrict__ X)
{
    int i = blockIdx.x * blockDim.x + threadIdx.x;
    int warp = i >> 5, lane = i & 31;

    // squared norms (fixed reduction order; warp-uniform loops)
#pragma unroll
    for (int r = 0; r < 2; r++) {
        int u = warp + r * 2048;
        const float* x = X + (size_t)u * FF;
        float s = 0.f;
#pragma unroll
        for (int k = 0; k < FF / 32; k++) { float a = x[lane + 32 * k]; s += a * a; }
#pragma unroll
        for (int o = 16; o; o >>= 1) s += __shfl_xor_sync(0xffffffffu, s, o);
        if (lane == 0) g_sq[u] = s;
    }

    if (i < NN) g_nbrCnt[i] = 0;
    if (i == 0) { g_S1 = 0ull; g_S2 = 0ull; }
    if (i < EE) {
        int u = ei[i];
        int v = ei[EE + i];
        atomicAdd(&g_A[(size_t)u * NN + v], w[i]);
    }
}

// dedup via atomicExch: winner gets the summed weight, cell is restored to 0.
__global__ void k_build(const int* __restrict__ ei)
{
    int i = blockIdx.x * blockDim.x + threadIdx.x;
    if (i >= EE) return;
    int u = ei[i];
    int v = ei[EE + i];
    float val = atomicExch(&g_A[(size_t)u * NN + v], 0.f);
    if (val != 0.f && u != v) {
        int p = atomicAdd(&g_nbrCnt[u], 1);
        if (p < MAXD - 1) {
            g_nbrCol[u * MAXD + p] = v;
            g_nbrVal[u * MAXD + p] = fminf(val, 1.f);   // clamp A>1 -> 1
        }
    }
}

// append diag (==1 exactly), finalize D, accumulate integer degree stats.
__global__ void k_diag()
{
    int u = blockIdx.x * blockDim.x + threadIdx.x;
    if (u >= NN) return;
    int c = g_nbrCnt[u]; if (c > MAXD - 1) c = MAXD - 1;
    g_nbrCol[u * MAXD + c] = u;
    g_nbrVal[u * MAXD + c] = 1.f;
    g_nbrCnt[u] = c + 1;
    g_D[u] = c;                                  // off-diag nonzero count
    atomicAdd(&g_S1, (unsigned long long)c);
    atomicAdd(&g_S2, (unsigned long long)((long long)c * c));
}

// Fused per-row kernel: SpGEMM row in smem (with first-touch compaction) ->
// branch -> O(Dr) radix select (parallel bin scan) -> sparse write.
__global__ void __launch_bounds__(256, 5) k_main(const float* __restrict__ X)
{
    __shared__ float    acc  [NN];     // 16 KB  A2 row accumulator
    __shared__ int      scol [MAXR];   //  8 KB
    __shared__ unsigned skey [MAXR];   //  8 KB  order-preserving distance keys
    __shared__ float    xu   [FF];     //  1 KB
    __shared__ int      ucol [MAXD];
    __shared__ float    uval [MAXD];
    __shared__ int      hist [256];    //  1 KB
    __shared__ int      wsum [8];
    __shared__ int      cntS, s_need, s_cGT;
    __shared__ unsigned s_prefix;
    __shared__ double   s_dth;

    int u      = blockIdx.x;
    int tid    = threadIdx.x;
    int warpid = tid >> 5, lane = tid & 31;

    {   // vectorized zero of acc
        float4 z = make_float4(0.f, 0.f, 0.f, 0.f);
        float4* a4 = reinterpret_cast<float4*>(acc);
#pragma unroll
        for (int i = 0; i < NN / 4 / 256; i++) a4[tid + 256 * i] = z;
    }
    int cnt = g_nbrCnt[u];
    if (tid < cnt) { ucol[tid] = g_nbrCol[u * MAXD + tid];
                     uval[tid] = g_nbrVal[u * MAXD + tid]; }
    for (int f = tid; f < FF; f += 256) xu[f] = X[(size_t)u * FF + f];
    if (tid == 0) {
        cntS = 0;
        // d_thres = mean(D) + 2*std(D) from exact integer sums
        double S1 = (double)g_S1, S2 = (double)g_S2;
        double mean = S1 / (double)NN;
        double var  = S2 / (double)NN - mean * mean;
        if (var < 0.0) var = 0.0;
        s_dth = mean + 2.0 * sqrt(var);
    }
    __syncthreads();

    // SpGEMM with fused compaction: atomicAdd returns old; exactly one thread
    // sees old==0 per column (per-address atomics serialize; products > 0),
    // and that thread appends the column. Order in scol is nondeterministic,
    // but all downstream use is set-based -> replay-consistent results.
    for (int t = warpid; t < cnt; t += 8) {
        int   k = ucol[t];
        float a = uval[t];
        int  ck = g_nbrCnt[k];
        const int*   kc = g_nbrCol + k * MAXD;
        const float* kv = g_nbrVal + k * MAXD;
        for (int e = lane; e < ck; e += 32) {
            int c = kc[e];
            float old = atomicAdd(&acc[c], a * kv[e]);
            if (old == 0.f && c != u) {
                int p = atomicAdd(&cntS, 1);
                if (p < MAXR) scol[p] = c;
            }
        }
    }
    __syncthreads();

    int Dr = cntS; if (Dr > MAXR) Dr = MAXR;
    int D  = g_D[u];
    bool highD = ((double)D > s_dth);
    int  nz    = Dr - 2 * D;

    float* outrow = g_A2 + (size_t)u * NN;

    if (highD) {
        // Z = (A == 0): keep A2-A only at 1-hop edges
        for (int i = tid; i < Dr; i += 256) {
            int c = scol[i];
            float a = 0.f;
            for (int j = 0; j < cnt; j++) if (ucol[j] == c) { a = uval[j]; break; }
            outrow[c] = (a != 0.f) ? (acc[c] - a) : 0.f;
        }
    } else if (nz < 0) {
        // no-sparse branch: adj_k = A2 - A everywhere
        for (int i = tid; i < Dr; i += 256) {
            int c = scol[i];
            float a = 0.f;
            for (int j = 0; j < cnt; j++) if (ucol[j] == c) { a = uval[j]; break; }
            outrow[c] = acc[c] - a;
        }
    } else if (nz == 0) {
        // nz_eff = n -> all neighbors selected -> entire row zero
        for (int i = tid; i < Dr; i += 256) outrow[scol[i]] = 0.f;
    } else {
        // sparse branch: zero the nz farthest (stable-tie) neighbors.
        float squ = g_sq[u];

        // Distances -> order-preserving uint keys.
        // Warp-uniform batches: 4 neighbors per warp-iteration (8-lane groups),
        // full-mask shuffles legal; 8 LDG.128/lane in flight.
        int grp4 = lane >> 3, gl = lane & 7;
        const float4* xu4 = reinterpret_cast<const float4*>(xu);
        for (int i0 = warpid * 4; i0 < Dr; i0 += 32) {
            int  i   = i0 + grp4;
            bool act = (i < Dr);
            int  v   = scol[act ? i : 0];     // Dr >= 1 in this branch
            const float4* xv4 = reinterpret_cast<const float4*>(X + (size_t)v * FF);
            float s = 0.f;
#pragma unroll
            for (int m = 0; m < 8; m++) {
                float4 a = xv4[gl + 8 * m];
                float4 b = xu4[gl + 8 * m];
                s += a.x * b.x;  s += a.y * b.y;
                s += a.z * b.z;  s += a.w * b.w;
            }
            s += __shfl_xor_sync(0xffffffffu, s, 4);
            s += __shfl_xor_sync(0xffffffffu, s, 2);
            s += __shfl_xor_sync(0xffffffffu, s, 1);
            if (gl == 0 && act) {
                float d = squ + g_sq[v] - 2.f * s;
                unsigned bits = __float_as_uint(d);
                unsigned key  = (bits & 0x80000000u) ? ~bits : (bits | 0x80000000u);
                if (key == 0x7FFFFFFFu) key = 0x80000000u;   // -0.0 == +0.0
                skey[i] = key;
            }
        }
        if (tid == 0) { s_prefix = 0u; s_need = nz; }
        __syncthreads();

        // Radix select: T = key of the nz-th largest element (1-indexed).
        // 4 byte-passes, high to low; bin chosen via PARALLEL suffix-sum.
#pragma unroll
        for (int pass = 0; pass < 4; pass++) {
            int shift = 24 - 8 * pass;
            hist[tid] = 0;                 // blockDim == 256 == #bins
            __syncthreads();
            unsigned pref = s_prefix;
            for (int i = tid; i < Dr; i += 256) {
                unsigned k = skey[i];
                bool in = (pass == 0) || ((k >> (shift + 8)) == pref);
                if (in) atomicAdd(&hist[(k >> shift) & 0xffu], 1);
            }
            __syncthreads();
            // suffix(b) for b = 255 - tid via inclusive scan of reversed hist
            int need = s_need;
            int val  = hist[255 - tid];
#pragma unroll
            for (int o = 1; o < 32; o <<= 1) {
                int n = __shfl_up_sync(0xffffffffu, val, o);
                if (lane >= o) val += n;
            }
            if (lane == 31) wsum[warpid] = val;
            __syncthreads();
            if (warpid == 0 && lane < 8) {
                int wv = wsum[lane];
#pragma unroll
                for (int o = 1; o < 8; o <<= 1) {
                    int n = __shfl_up_sync(0x000000ffu, wv, o);
                    if (lane >= o) wv += n;
                }
                wsum[lane] = wv;
            }
            __syncthreads();
            int P     = val + (warpid ? wsum[warpid - 1] : 0);  // suffix(255-tid)
            int Pexcl = P - hist[255 - tid];                    // suffix(256-tid)
            if (P >= need && Pexcl < need) {        // unique winner
                s_prefix = (s_prefix << 8) | (unsigned)(255 - tid);
                s_need   = need - Pexcl;
            }
            __syncthreads();
        }
        unsigned T = s_prefix;

        // cGT = #{key > T} (exact integer count, order-free)
        if (tid == 0) s_cGT = 0;
        __syncthreads();
        {
            int local = 0;
            for (int i = tid; i < Dr; i += 256) local += (skey[i] > T);
#pragma unroll
            for (int o = 16; o; o >>= 1) local += __shfl_xor_sync(0xffffffffu, local, o);
            if (lane == 0 && local) atomicAdd(&s_cGT, local);
        }
        __syncthreads();
        int tieSel = nz - s_cGT;    // slots left for ties, filled by ascending col

        for (int i = tid; i < Dr; i += 256) {
            unsigned k  = skey[i];
            int      ci = scol[i];
            bool zero;
            if (k > T) zero = true;
            else if (k == T) {
                int tr = 0;
                for (int j = 0; j < Dr; j++)
                    tr += (skey[j] == T && scol[j] < ci);
                zero = (tr < tieSel);
            } else zero = false;

            float out;
            if (zero) out = 0.f;
            else {
                float a = 0.f;
                for (int t = 0; t < cnt; t++) if (ucol[t] == ci) { a = uval[t]; break; }
                out = acc[ci] - a;
            }
            outrow[ci] = out;
        }
    }
    // diag of adj_k is 0: never written -> stays 0 from static init
}

__global__ void k_edge(const int* __restrict__ ei, const float* __restrict__ w,
                       const float* __restrict__ t1, const float* __restrict__ t2,
                       float* __restrict__ out)
{
    int i = blockIdx.x * blockDim.x + threadIdx.x;
    if (i < EE) {
        int u = ei[i];
        int v = ei[EE + i];
        float val = t1[0] * w[i] + t2[0] * g_A2[(size_t)u * NN + v];
        out[i] = fmaxf(val, 0.f);
    }
}

// ---------------- launch ------------------------------------------------------

extern "C" void kernel_launch(void* const* d_in, const int* in_sizes, int n_in,
                              void* d_out, int out_size)
{
    (void)in_sizes; (void)n_in; (void)out_size;
    const int*   edge_index = (const int*)  d_in[0];   // (2, E) int32
    const float* edge_w     = (const float*)d_in[1];   // (E,)
    const float* features   = (const float*)d_in[2];   // (N, F)
    const float* theta_1    = (const float*)d_in[3];   // (1,)
    const float* theta_2    = (const float*)d_in[4];   // (1,)
    float*       out        = (float*)      d_out;     // (E,)

    k_scatter<<<EE / 256, 256>>>(edge_index, edge_w, features);
    k_build  <<<EE / 256, 256>>>(edge_index);
    k_diag   <<<NN / 256, 256>>>();
    k_main   <<<NN,       256>>>(features);
    k_edge   <<<EE / 256, 256>>>(edge_index, edge_w, theta_1, theta_2, out);
}